// round 16
// baseline (speedup 1.0000x reference)
#include <cuda_runtime.h>
#include <cuda_bf16.h>
#include <math.h>
#include <cstdint>

#define BATCH 128
#define SEQ   4096
#define SD    5
#define HID   32
#define DIN   9
#define NTOK  (BATCH*SEQ)
#define TPB   128
#define TOKS_PER_BLOCK 512
#define FPITCH 48     // feature tile row pitch (32B data + 16 pad, 16B-aligned)
#define WPITCH 80     // weight tile pitch (proven conflict-free for ldmatrix)

__device__ float g_temp[NTOK];

typedef unsigned long long ull;

__device__ __forceinline__ ull pk(float lo, float hi) {
    ull r; asm("mov.b64 %0, {%1, %2};" : "=l"(r) : "f"(lo), "f"(hi)); return r;
}
__device__ __forceinline__ void upk(float& lo, float& hi, ull v) {
    asm("mov.b64 {%0, %1}, %2;" : "=f"(lo), "=f"(hi) : "l"(v));
}
__device__ __forceinline__ void ffma2(ull& d, ull a, ull b) {
    asm("fma.rn.f32x2 %0, %1, %2, %0;" : "+l"(d) : "l"(a), "l"(b));
}
__device__ __forceinline__ ull add2(ull a, ull b) {
    ull r; asm("add.rn.f32x2 %0, %1, %2;" : "=l"(r) : "l"(a), "l"(b)); return r;
}
__device__ __forceinline__ ull dup(float x) { return pk(x, x); }
__device__ __forceinline__ float tanh_apx(float x) {
    float y; asm("tanh.approx.f32 %0, %1;" : "=f"(y) : "f"(x)); return y;
}
__device__ __forceinline__ unsigned int pk_bf2(float lo, float hi) {
    unsigned int r;
    asm("cvt.rn.bf16x2.f32 %0, %1, %2;" : "=r"(r) : "f"(hi), "f"(lo));
    return r;
}
__device__ __forceinline__ uint32_t smem_u32(const void* p) {
    uint32_t a;
    asm("{ .reg .u64 t; cvta.to.shared.u64 t, %1; cvt.u32.u64 %0, t; }"
        : "=r"(a) : "l"(p));
    return a;
}
__device__ __forceinline__ void ldmatrix_x4(uint32_t& r0, uint32_t& r1,
                                            uint32_t& r2, uint32_t& r3,
                                            uint32_t addr) {
    asm volatile("ldmatrix.sync.aligned.m8n8.x4.shared.b16 {%0,%1,%2,%3}, [%4];"
                 : "=r"(r0), "=r"(r1), "=r"(r2), "=r"(r3) : "r"(addr));
}
__device__ __forceinline__ void mma_bf16(float* d, const uint32_t* a,
                                         uint32_t b0, uint32_t b1) {
    asm volatile(
        "mma.sync.aligned.m16n8k16.row.col.f32.bf16.bf16.f32 "
        "{%0,%1,%2,%3}, {%4,%5,%6,%7}, {%8,%9}, {%0,%1,%2,%3};"
        : "+f"(d[0]), "+f"(d[1]), "+f"(d[2]), "+f"(d[3])
        : "r"(a[0]), "r"(a[1]), "r"(a[2]), "r"(a[3]), "r"(b0), "r"(b1));
}

// -------------------------------------------------------------------------
// Kernel 1: per-batch-row inclusive cumsum of delta_x[..., 2] + init temp
// -------------------------------------------------------------------------
__global__ __launch_bounds__(1024) void cumsum_kernel(const float* __restrict__ dx) {
    __shared__ float wsum[32];
    const int b    = blockIdx.x;
    const int tid  = threadIdx.x;
    const int lane = tid & 31;
    const int wid  = tid >> 5;
    const float* row = dx + (size_t)b * SEQ * 6;

    const int s0 = tid * 4;
    float v0 = row[(s0 + 0) * 6 + 2];
    float v1 = row[(s0 + 1) * 6 + 2];
    float v2 = row[(s0 + 2) * 6 + 2];
    float v3 = row[(s0 + 3) * 6 + 2];
    float p0 = v0, p1 = p0 + v1, p2 = p1 + v2, p3 = p2 + v3;
    float tot = p3;

    float s = tot;
    #pragma unroll
    for (int off = 1; off < 32; off <<= 1) {
        float n = __shfl_up_sync(0xffffffffu, s, off);
        if (lane >= off) s += n;
    }
    if (lane == 31) wsum[wid] = s;
    __syncthreads();
    if (wid == 0) {
        float w = wsum[lane];
        #pragma unroll
        for (int off = 1; off < 32; off <<= 1) {
            float n = __shfl_up_sync(0xffffffffu, w, off);
            if (lane >= off) w += n;
        }
        wsum[lane] = w;
    }
    __syncthreads();

    float base = row[5] + (s - tot) + ((wid > 0) ? wsum[wid - 1] : 0.0f);
    float* outp = g_temp + (size_t)b * SEQ + s0;
    outp[0] = base + p0; outp[1] = base + p1;
    outp[2] = base + p2; outp[3] = base + p3;
}

// -------------------------------------------------------------------------
// Kernel 2: fully tensorized two-layer gated MLP.
//   features: 16 bf16 limbs (h hi/lo, temp 3 limbs, dir) -> smem tile
//   L0: mma [32x16]@[16x64] hi + lo weight limbs (A chunk reused)
//   u: tanh*tanh on D fragments, repacked in-register as L1 A fragments
//   L1: mma with W1 hi+lo; epilogue/heads/tail = R15 verbatim
// -------------------------------------------------------------------------
// dynamic smem offsets
#define SM_FEAT  0            // 512*48 = 24576
#define SM_W0B   24576        // 64*80  = 5120
#define SM_W1H   29696        // 5120
#define SM_W1L   34816        // 5120
#define SM_BA0   39936        // 32 f
#define SM_BB0   40064
#define SM_B1A   40192
#define SM_B1B   40320
#define SM_H     40448        // 32*4 ull = 1024
#define SM_AINIT 41472        // 4 ull
#define SM_WOUT  41504        // 5 f
#define SM_TOTAL 41536

__global__ __launch_bounds__(TPB) void msc_main(
    const float* __restrict__ h_prev,  const float* __restrict__ delta_x,
    const float* __restrict__ Wa0,     const float* __restrict__ ba0,
    const float* __restrict__ Wb0,     const float* __restrict__ bb0,
    const float* __restrict__ Wa1,     const float* __restrict__ ba1,
    const float* __restrict__ Wb1,     const float* __restrict__ bb1,
    const float* __restrict__ W_alpha, const float* __restrict__ b_alpha,
    const float* __restrict__ W_beta,  const float* __restrict__ b_beta,
    const float* __restrict__ W_gamma, const float* __restrict__ b_gamma,
    const float* __restrict__ W_c,     const float* __restrict__ b_c,
    const float* __restrict__ W_out,
    float* __restrict__ out)
{
    extern __shared__ __align__(16) unsigned char smem[];
    float* ba0s  = (float*)(smem + SM_BA0);
    float* bb0s  = (float*)(smem + SM_BB0);
    float* b1as  = (float*)(smem + SM_B1A);
    float* b1bs  = (float*)(smem + SM_B1B);
    ull*   sH    = (ull*)(smem + SM_H);
    ull*   sAin  = (ull*)(smem + SM_AINIT);
    float* sWout = (float*)(smem + SM_WOUT);

    const int tid  = threadIdx.x;
    const int lane = tid & 31;
    const int w    = tid >> 5;
    const int q    = lane & 3;

    // ---- stage W0 B-tile: 64 n-rows x 32 k (k<16 hi limb, k>=16 lo limb) ----
    for (int e = tid; e < 64 * 32; e += TPB) {
        int n = e >> 5, k = e & 31;
        int limb = k >> 4, kk = k & 15;
        int i = (kk < 5) ? kk : (kk < 10 ? kk - 5 : (kk < 13 ? 5 : kk - 7));
        float wv = (n < HID) ? Wa0[i * HID + n] : Wb0[i * HID + (n - HID)];
        __nv_bfloat16 hi = __float2bfloat16(wv);
        __nv_bfloat16 val = limb ? __float2bfloat16(wv - __bfloat162float(hi)) : hi;
        *(__nv_bfloat16*)(smem + SM_W0B + n * WPITCH + k * 2) = val;
    }
    // ---- stage W1 hi/lo (as R15) ----
    for (int e = tid; e < 64 * HID; e += TPB) {
        int n = e >> 5, k = e & 31;
        float wv = (n < HID) ? Wa1[k * HID + n] : Wb1[k * HID + (n - HID)];
        __nv_bfloat16 bh = __float2bfloat16(wv);
        __nv_bfloat16 bl = __float2bfloat16(wv - __bfloat162float(bh));
        *(__nv_bfloat16*)(smem + SM_W1H + n * WPITCH + k * 2) = bh;
        *(__nv_bfloat16*)(smem + SM_W1L + n * WPITCH + k * 2) = bl;
    }
    if (tid < HID) {
        ba0s[tid] = ba0[tid];  bb0s[tid] = bb0[tid];
        b1as[tid] = ba1[tid];  b1bs[tid] = bb1[tid];
        sH[tid * 4 + 0] = pk(W_alpha[tid],       W_beta[tid]);
        sH[tid * 4 + 1] = pk(W_gamma[tid],       W_c[tid * SD + 0]);
        sH[tid * 4 + 2] = pk(W_c[tid * SD + 1],  W_c[tid * SD + 2]);
        sH[tid * 4 + 3] = pk(W_c[tid * SD + 3],  W_c[tid * SD + 4]);
    }
    if (tid == 0) {
        sAin[0] = pk(b_alpha[0], b_beta[0]);
        sAin[1] = pk(b_gamma[0], b_c[0]);
        sAin[2] = pk(b_c[1],     b_c[2]);
        sAin[3] = pk(b_c[3],     b_c[4]);
    }
    if (tid < SD) sWout[tid] = W_out[tid];
    __syncthreads();

    const int tb = blockIdx.x * TOKS_PER_BLOCK;

    // ---- build 16-feature bf16 rows (limb-split) for 4 tokens ----
    #pragma unroll
    for (int k = 0; k < 4; k++) {
        const int t = tb + k * TPB + tid;
        const float* hp  = h_prev  + (size_t)t * SD;
        const float* dxp = delta_x + (size_t)t * 6;
        float h0 = hp[0], h1 = hp[1], h2 = hp[2], h3 = hp[3], h4 = hp[4];
        float d0 = dxp[0], d1 = dxp[1], d2 = dxp[2];
        float nrm = sqrtf(fmaf(d0, d0, fmaf(d1, d1, d2 * d2)));
        nrm = fmaxf(nrm, 1e-7f);
        float inv = __fdividef(1.0f, nrm);
        float dn0 = d0 * inv, dn1 = d1 * inv, dn2 = d2 * inv;
        float tf  = g_temp[t];

        float rh0 = h0 - __bfloat162float(__float2bfloat16(h0));
        float rh1 = h1 - __bfloat162float(__float2bfloat16(h1));
        float rh2 = h2 - __bfloat162float(__float2bfloat16(h2));
        float rh3 = h3 - __bfloat162float(__float2bfloat16(h3));
        float rh4 = h4 - __bfloat162float(__float2bfloat16(h4));
        float rt1 = tf  - __bfloat162float(__float2bfloat16(tf));
        float rt2 = rt1 - __bfloat162float(__float2bfloat16(rt1));

        uint4 A, B;
        A.x = pk_bf2(h0, h1);   A.y = pk_bf2(h2, h3);
        A.z = pk_bf2(h4, rh0);  A.w = pk_bf2(rh1, rh2);
        B.x = pk_bf2(rh3, rh4); B.y = pk_bf2(tf, rt1);
        B.z = pk_bf2(rt2, dn0); B.w = pk_bf2(dn1, dn2);
        unsigned char* base = smem + SM_FEAT + (size_t)(k * TPB + tid) * FPITCH;
        *(uint4*)(base)      = A;
        *(uint4*)(base + 16) = B;
    }
    __syncwarp();   // warp consumes only its own rows

    // ---- per-lane biases (j-set shared by L0 and L1 epilogues) ----
    float myBa0[8], myBb0[8], myBa1[8], myBb1[8];
    #pragma unroll
    for (int p = 0; p < 8; p++) {
        const int j = (p >> 1) * 8 + 2 * q + (p & 1);
        myBa0[p] = ba0s[j];  myBb0[p] = bb0s[j];
        myBa1[p] = b1as[j];  myBb1[p] = b1bs[j];
    }

    const uint32_t f_base   = smem_u32(smem + SM_FEAT);
    const uint32_t w0_base  = smem_u32(smem + SM_W0B);
    const uint32_t w1h_base = smem_u32(smem + SM_W1H);
    const uint32_t w1l_base = smem_u32(smem + SM_W1L);

    #pragma unroll 1
    for (int T = 0; T < 4; T++) {
        // ---- L0 A fragments (16 features; reused for both B k-chunks) ----
        uint32_t Af0[2][4];
        #pragma unroll
        for (int mt = 0; mt < 2; mt++) {
            uint32_t addr = f_base
                + (uint32_t)(T * TPB + w * 32 + mt * 16 + (lane & 15)) * FPITCH
                + (lane >> 4) * 16;
            ldmatrix_x4(Af0[mt][0], Af0[mt][1], Af0[mt][2], Af0[mt][3], addr);
        }
        // ---- L0 B fragments (hi = kt0, lo = kt1) ----
        uint32_t Bf[8][2][2];
        #pragma unroll
        for (int kt = 0; kt < 2; kt++) {
            #pragma unroll
            for (int g = 0; g < 4; g++) {
                const int m  = lane >> 3;
                const int nt = 2 * g + (m >> 1);
                const int kq = m & 1;
                uint32_t off = (uint32_t)(nt * 8 + (lane & 7)) * WPITCH
                             + kt * 32 + kq * 16;
                ldmatrix_x4(Bf[2 * g][kt][0], Bf[2 * g][kt][1],
                            Bf[2 * g + 1][kt][0], Bf[2 * g + 1][kt][1],
                            w0_base + off);
            }
        }
        // ---- L0 MMA: D = A@W0hi + A@W0lo ----
        float d0[2][8][4];
        #pragma unroll
        for (int mt = 0; mt < 2; mt++)
            #pragma unroll
            for (int nt = 0; nt < 8; nt++) {
                #pragma unroll
                for (int c = 0; c < 4; c++) d0[mt][nt][c] = 0.0f;
                mma_bf16(d0[mt][nt], Af0[mt], Bf[nt][0][0], Bf[nt][0][1]);
                mma_bf16(d0[mt][nt], Af0[mt], Bf[nt][1][0], Bf[nt][1][1]);
            }
        // ---- u = tanh*tanh on fragments ----
        float u[2][4][4];
        #pragma unroll
        for (int mt = 0; mt < 2; mt++)
            #pragma unroll
            for (int nt = 0; nt < 4; nt++)
                #pragma unroll
                for (int c = 0; c < 4; c++) {
                    const int p = nt * 2 + (c & 1);
                    const float apre = d0[mt][nt][c]     + myBa0[p];
                    const float bpre = d0[mt][nt + 4][c] + myBb0[p];
                    u[mt][nt][c] = tanh_apx(apre) * tanh_apx(bpre);
                }
        // ---- repack u as L1 A fragments (in-register, no smem) ----
        uint32_t Af1[2][2][4];
        #pragma unroll
        for (int mt = 0; mt < 2; mt++)
            #pragma unroll
            for (int kt = 0; kt < 2; kt++) {
                Af1[mt][kt][0] = pk_bf2(u[mt][2 * kt][0],     u[mt][2 * kt][1]);
                Af1[mt][kt][1] = pk_bf2(u[mt][2 * kt][2],     u[mt][2 * kt][3]);
                Af1[mt][kt][2] = pk_bf2(u[mt][2 * kt + 1][0], u[mt][2 * kt + 1][1]);
                Af1[mt][kt][3] = pk_bf2(u[mt][2 * kt + 1][2], u[mt][2 * kt + 1][3]);
            }
        // ---- L1 MMA: D = u@W1hi + u@W1lo (two passes reuse Bf regs) ----
        float d1[2][8][4];
        #pragma unroll
        for (int mt = 0; mt < 2; mt++)
            #pragma unroll
            for (int nt = 0; nt < 8; nt++)
                #pragma unroll
                for (int c = 0; c < 4; c++) d1[mt][nt][c] = 0.0f;

        #pragma unroll
        for (int pass = 0; pass < 2; pass++) {
            const uint32_t wb = pass ? w1l_base : w1h_base;
            #pragma unroll
            for (int kt = 0; kt < 2; kt++) {
                #pragma unroll
                for (int g = 0; g < 4; g++) {
                    const int m  = lane >> 3;
                    const int nt = 2 * g + (m >> 1);
                    const int kq = m & 1;
                    uint32_t off = (uint32_t)(nt * 8 + (lane & 7)) * WPITCH
                                 + kt * 32 + kq * 16;
                    ldmatrix_x4(Bf[2 * g][kt][0], Bf[2 * g][kt][1],
                                Bf[2 * g + 1][kt][0], Bf[2 * g + 1][kt][1],
                                wb + off);
                }
            }
            #pragma unroll
            for (int mt = 0; mt < 2; mt++)
                #pragma unroll
                for (int nt = 0; nt < 8; nt++) {
                    mma_bf16(d1[mt][nt], Af1[mt][0], Bf[nt][0][0], Bf[nt][0][1]);
                    mma_bf16(d1[mt][nt], Af1[mt][1], Bf[nt][1][0], Bf[nt][1][1]);
                }
        }

        // ---- v = tanh*tanh (R15 layout) ----
        float vv[4][8];
        #pragma unroll
        for (int s = 0; s < 4; s++) {
            const int mt = s >> 1, co = (s & 1) * 2;
            #pragma unroll
            for (int p = 0; p < 8; p++) {
                const int nt = p >> 1, e = p & 1;
                const float apre = d1[mt][nt][co + e]     + myBa1[p];
                const float bpre = d1[mt][nt + 4][co + e] + myBb1[p];
                vv[s][p] = tanh_apx(apre) * tanh_apx(bpre);
            }
        }

        // ---- heads partial sums ----
        ull H[4][4];
        #pragma unroll
        for (int s = 0; s < 4; s++)
            #pragma unroll
            for (int m = 0; m < 4; m++) H[s][m] = 0ULL;

        #pragma unroll
        for (int p = 0; p < 8; p++) {
            const int j = (p >> 1) * 8 + 2 * q + (p & 1);
            const ull hw0 = sH[j * 4 + 0], hw1 = sH[j * 4 + 1];
            const ull hw2 = sH[j * 4 + 2], hw3 = sH[j * 4 + 3];
            #pragma unroll
            for (int s = 0; s < 4; s++) {
                const ull vd = dup(vv[s][p]);
                ffma2(H[s][0], vd, hw0);
                ffma2(H[s][1], vd, hw1);
                ffma2(H[s][2], vd, hw2);
                ffma2(H[s][3], vd, hw3);
            }
        }

        // ---- butterfly reduce over the 4-lane column group ----
        #pragma unroll
        for (int mask = 1; mask <= 2; mask <<= 1) {
            #pragma unroll
            for (int s = 0; s < 4; s++)
                #pragma unroll
                for (int m = 0; m < 4; m++) {
                    ull o = __shfl_xor_sync(0xffffffffu, H[s][m], mask);
                    H[s][m] = add2(H[s][m], o);
                }
        }

        // ---- tail: lane handles token slot q ----
        {
            const int r = ((q >> 1) * 16) + ((q & 1) * 8) + (lane >> 2);
            const int t = tb + T * TPB + w * 32 + r;

            const ull Hf0 = add2(H[q][0], sAin[0]);
            const ull Hf1 = add2(H[q][1], sAin[1]);
            const ull Hf2 = add2(H[q][2], sAin[2]);
            const ull Hf3 = add2(H[q][3], sAin[3]);

            float sa, sb, sg, c0, c1, c2, c3, c4;
            upk(sa, sb, Hf0);
            upk(sg, c0, Hf1);
            upk(c1, c2, Hf2);
            upk(c3, c4, Hf3);

            const float* dxp = delta_x + (size_t)t * 6;
            const float* hp  = h_prev  + (size_t)t * SD;
            const float d0x = dxp[0], d1x = dxp[1], d2x = dxp[2];

            const float alpha = __expf(sa);
            const float beta  = __expf(sb);
            const float gamma = __expf(sg);
            const float zarg = fmaf(alpha, fabsf(d0x), fmaf(beta, d1x, gamma * fabsf(d2x)));
            const float z = 1.0f - __expf(-zarg);

            float c[SD] = { c0, c1, c2, c3, c4 };
            float sigma = 0.0f;
            #pragma unroll
            for (int dd = 0; dd < SD; dd++) {
                const float hv = hp[dd];
                const float cn = tanh_apx(c[dd]);
                const float hn = fmaf(z, cn - hv, hv);
                out[(size_t)t * SD + dd] = hn;
                sigma = fmaf(hn, sWout[dd], sigma);
            }
            out[(size_t)NTOK * SD + t] = sigma;
        }
    }
}

extern "C" void kernel_launch(void* const* d_in, const int* in_sizes, int n_in,
                              void* d_out, int out_size) {
    const float* h_prev  = (const float*)d_in[0];
    const float* delta_x = (const float*)d_in[1];
    const float* Wa0     = (const float*)d_in[2];
    const float* ba0     = (const float*)d_in[3];
    const float* Wb0     = (const float*)d_in[4];
    const float* bb0     = (const float*)d_in[5];
    const float* Wa1     = (const float*)d_in[6];
    const float* ba1     = (const float*)d_in[7];
    const float* Wb1     = (const float*)d_in[8];
    const float* bb1     = (const float*)d_in[9];
    const float* W_alpha = (const float*)d_in[10];
    const float* b_alpha = (const float*)d_in[11];
    const float* W_beta  = (const float*)d_in[12];
    const float* b_beta  = (const float*)d_in[13];
    const float* W_gamma = (const float*)d_in[14];
    const float* b_gamma = (const float*)d_in[15];
    const float* W_c     = (const float*)d_in[16];
    const float* b_c     = (const float*)d_in[17];
    const float* W_out   = (const float*)d_in[18];
    float* out = (float*)d_out;

    cumsum_kernel<<<BATCH, 1024>>>(delta_x);
    msc_main<<<NTOK / TOKS_PER_BLOCK, TPB, SM_TOTAL>>>(
        h_prev, delta_x,
        Wa0, ba0, Wb0, bb0,
        Wa1, ba1, Wb1, bb1,
        W_alpha, b_alpha, W_beta, b_beta,
        W_gamma, b_gamma, W_c, b_c, W_out,
        out);
}

// round 17
// speedup vs baseline: 1.1759x; 1.1759x over previous
#include <cuda_runtime.h>
#include <cuda_bf16.h>
#include <math.h>
#include <cstdint>

#define BATCH 128
#define SEQ   4096
#define SD    5
#define HID   32
#define DIN   9
#define NTOK  (BATCH*SEQ)
#define TPB   128
#define TOKS_PER_BLOCK 512
#define FPITCH 48     // feature tile row pitch (32B data + 16 pad, 16B-aligned)
#define WPITCH 80     // weight tile pitch (proven conflict-free for ldmatrix)

__device__ float g_temp[NTOK];

typedef unsigned long long ull;

__device__ __forceinline__ ull pk(float lo, float hi) {
    ull r; asm("mov.b64 %0, {%1, %2};" : "=l"(r) : "f"(lo), "f"(hi)); return r;
}
__device__ __forceinline__ void upk(float& lo, float& hi, ull v) {
    asm("mov.b64 {%0, %1}, %2;" : "=f"(lo), "=f"(hi) : "l"(v));
}
__device__ __forceinline__ void ffma2(ull& d, ull a, ull b) {
    asm("fma.rn.f32x2 %0, %1, %2, %0;" : "+l"(d) : "l"(a), "l"(b));
}
__device__ __forceinline__ ull add2(ull a, ull b) {
    ull r; asm("add.rn.f32x2 %0, %1, %2;" : "=l"(r) : "l"(a), "l"(b)); return r;
}
__device__ __forceinline__ ull dup(float x) { return pk(x, x); }
__device__ __forceinline__ float tanh_apx(float x) {
    float y; asm("tanh.approx.f32 %0, %1;" : "=f"(y) : "f"(x)); return y;
}
__device__ __forceinline__ unsigned int pk_bf2(float lo, float hi) {
    unsigned int r;
    asm("cvt.rn.bf16x2.f32 %0, %1, %2;" : "=r"(r) : "f"(hi), "f"(lo));
    return r;
}
__device__ __forceinline__ uint32_t smem_u32(const void* p) {
    uint32_t a;
    asm("{ .reg .u64 t; cvta.to.shared.u64 t, %1; cvt.u32.u64 %0, t; }"
        : "=r"(a) : "l"(p));
    return a;
}
__device__ __forceinline__ void ldmatrix_x4(uint32_t& r0, uint32_t& r1,
                                            uint32_t& r2, uint32_t& r3,
                                            uint32_t addr) {
    asm volatile("ldmatrix.sync.aligned.m8n8.x4.shared.b16 {%0,%1,%2,%3}, [%4];"
                 : "=r"(r0), "=r"(r1), "=r"(r2), "=r"(r3) : "r"(addr));
}
__device__ __forceinline__ void mma_bf16(float* d, const uint32_t* a,
                                         uint32_t b0, uint32_t b1) {
    asm volatile(
        "mma.sync.aligned.m16n8k16.row.col.f32.bf16.bf16.f32 "
        "{%0,%1,%2,%3}, {%4,%5,%6,%7}, {%8,%9}, {%0,%1,%2,%3};"
        : "+f"(d[0]), "+f"(d[1]), "+f"(d[2]), "+f"(d[3])
        : "r"(a[0]), "r"(a[1]), "r"(a[2]), "r"(a[3]), "r"(b0), "r"(b1));
}

// -------------------------------------------------------------------------
// Kernel 1: per-batch-row inclusive cumsum of delta_x[..., 2] + init temp
// -------------------------------------------------------------------------
__global__ __launch_bounds__(1024) void cumsum_kernel(const float* __restrict__ dx) {
    __shared__ float wsum[32];
    const int b    = blockIdx.x;
    const int tid  = threadIdx.x;
    const int lane = tid & 31;
    const int wid  = tid >> 5;
    const float* row = dx + (size_t)b * SEQ * 6;

    const int s0 = tid * 4;
    float v0 = row[(s0 + 0) * 6 + 2];
    float v1 = row[(s0 + 1) * 6 + 2];
    float v2 = row[(s0 + 2) * 6 + 2];
    float v3 = row[(s0 + 3) * 6 + 2];
    float p0 = v0, p1 = p0 + v1, p2 = p1 + v2, p3 = p2 + v3;
    float tot = p3;

    float s = tot;
    #pragma unroll
    for (int off = 1; off < 32; off <<= 1) {
        float n = __shfl_up_sync(0xffffffffu, s, off);
        if (lane >= off) s += n;
    }
    if (lane == 31) wsum[wid] = s;
    __syncthreads();
    if (wid == 0) {
        float w = wsum[lane];
        #pragma unroll
        for (int off = 1; off < 32; off <<= 1) {
            float n = __shfl_up_sync(0xffffffffu, w, off);
            if (lane >= off) w += n;
        }
        wsum[lane] = w;
    }
    __syncthreads();

    float base = row[5] + (s - tot) + ((wid > 0) ? wsum[wid - 1] : 0.0f);
    float* outp = g_temp + (size_t)b * SEQ + s0;
    outp[0] = base + p0; outp[1] = base + p1;
    outp[2] = base + p2; outp[3] = base + p3;
}

// -------------------------------------------------------------------------
// Kernel 2: fully tensorized two-layer gated MLP (R16) at 4 blocks/SM.
// -------------------------------------------------------------------------
// dynamic smem offsets
#define SM_FEAT  0            // 512*48 = 24576
#define SM_W0B   24576        // 64*80  = 5120
#define SM_W1H   29696        // 5120
#define SM_W1L   34816        // 5120
#define SM_BA0   39936        // 32 f
#define SM_BB0   40064
#define SM_B1A   40192
#define SM_B1B   40320
#define SM_H     40448        // 32*4 ull = 1024
#define SM_AINIT 41472        // 4 ull
#define SM_WOUT  41504        // 5 f
#define SM_TOTAL 41536

__global__ __launch_bounds__(TPB, 4) void msc_main(
    const float* __restrict__ h_prev,  const float* __restrict__ delta_x,
    const float* __restrict__ Wa0,     const float* __restrict__ ba0,
    const float* __restrict__ Wb0,     const float* __restrict__ bb0,
    const float* __restrict__ Wa1,     const float* __restrict__ ba1,
    const float* __restrict__ Wb1,     const float* __restrict__ bb1,
    const float* __restrict__ W_alpha, const float* __restrict__ b_alpha,
    const float* __restrict__ W_beta,  const float* __restrict__ b_beta,
    const float* __restrict__ W_gamma, const float* __restrict__ b_gamma,
    const float* __restrict__ W_c,     const float* __restrict__ b_c,
    const float* __restrict__ W_out,
    float* __restrict__ out)
{
    extern __shared__ __align__(16) unsigned char smem[];
    float* ba0s  = (float*)(smem + SM_BA0);
    float* bb0s  = (float*)(smem + SM_BB0);
    float* b1as  = (float*)(smem + SM_B1A);
    float* b1bs  = (float*)(smem + SM_B1B);
    ull*   sH    = (ull*)(smem + SM_H);
    ull*   sAin  = (ull*)(smem + SM_AINIT);
    float* sWout = (float*)(smem + SM_WOUT);

    const int tid  = threadIdx.x;
    const int lane = tid & 31;
    const int w    = tid >> 5;
    const int q    = lane & 3;

    // ---- stage W0 B-tile: 64 n-rows x 32 k (k<16 hi limb, k>=16 lo limb) ----
    for (int e = tid; e < 64 * 32; e += TPB) {
        int n = e >> 5, k = e & 31;
        int limb = k >> 4, kk = k & 15;
        int i = (kk < 5) ? kk : (kk < 10 ? kk - 5 : (kk < 13 ? 5 : kk - 7));
        float wv = (n < HID) ? Wa0[i * HID + n] : Wb0[i * HID + (n - HID)];
        __nv_bfloat16 hi = __float2bfloat16(wv);
        __nv_bfloat16 val = limb ? __float2bfloat16(wv - __bfloat162float(hi)) : hi;
        *(__nv_bfloat16*)(smem + SM_W0B + n * WPITCH + k * 2) = val;
    }
    // ---- stage W1 hi/lo ----
    for (int e = tid; e < 64 * HID; e += TPB) {
        int n = e >> 5, k = e & 31;
        float wv = (n < HID) ? Wa1[k * HID + n] : Wb1[k * HID + (n - HID)];
        __nv_bfloat16 bh = __float2bfloat16(wv);
        __nv_bfloat16 bl = __float2bfloat16(wv - __bfloat162float(bh));
        *(__nv_bfloat16*)(smem + SM_W1H + n * WPITCH + k * 2) = bh;
        *(__nv_bfloat16*)(smem + SM_W1L + n * WPITCH + k * 2) = bl;
    }
    if (tid < HID) {
        ba0s[tid] = ba0[tid];  bb0s[tid] = bb0[tid];
        b1as[tid] = ba1[tid];  b1bs[tid] = bb1[tid];
        sH[tid * 4 + 0] = pk(W_alpha[tid],       W_beta[tid]);
        sH[tid * 4 + 1] = pk(W_gamma[tid],       W_c[tid * SD + 0]);
        sH[tid * 4 + 2] = pk(W_c[tid * SD + 1],  W_c[tid * SD + 2]);
        sH[tid * 4 + 3] = pk(W_c[tid * SD + 3],  W_c[tid * SD + 4]);
    }
    if (tid == 0) {
        sAin[0] = pk(b_alpha[0], b_beta[0]);
        sAin[1] = pk(b_gamma[0], b_c[0]);
        sAin[2] = pk(b_c[1],     b_c[2]);
        sAin[3] = pk(b_c[3],     b_c[4]);
    }
    if (tid < SD) sWout[tid] = W_out[tid];
    __syncthreads();

    const int tb = blockIdx.x * TOKS_PER_BLOCK;

    // ---- build 16-feature bf16 rows (limb-split) for 4 tokens ----
    #pragma unroll
    for (int k = 0; k < 4; k++) {
        const int t = tb + k * TPB + tid;
        const float* hp  = h_prev  + (size_t)t * SD;
        const float* dxp = delta_x + (size_t)t * 6;
        float h0 = hp[0], h1 = hp[1], h2 = hp[2], h3 = hp[3], h4 = hp[4];
        float d0 = dxp[0], d1 = dxp[1], d2 = dxp[2];
        float nrm = sqrtf(fmaf(d0, d0, fmaf(d1, d1, d2 * d2)));
        nrm = fmaxf(nrm, 1e-7f);
        float inv = __fdividef(1.0f, nrm);
        float dn0 = d0 * inv, dn1 = d1 * inv, dn2 = d2 * inv;
        float tf  = g_temp[t];

        float rh0 = h0 - __bfloat162float(__float2bfloat16(h0));
        float rh1 = h1 - __bfloat162float(__float2bfloat16(h1));
        float rh2 = h2 - __bfloat162float(__float2bfloat16(h2));
        float rh3 = h3 - __bfloat162float(__float2bfloat16(h3));
        float rh4 = h4 - __bfloat162float(__float2bfloat16(h4));
        float rt1 = tf  - __bfloat162float(__float2bfloat16(tf));
        float rt2 = rt1 - __bfloat162float(__float2bfloat16(rt1));

        uint4 A, B;
        A.x = pk_bf2(h0, h1);   A.y = pk_bf2(h2, h3);
        A.z = pk_bf2(h4, rh0);  A.w = pk_bf2(rh1, rh2);
        B.x = pk_bf2(rh3, rh4); B.y = pk_bf2(tf, rt1);
        B.z = pk_bf2(rt2, dn0); B.w = pk_bf2(dn1, dn2);
        unsigned char* base = smem + SM_FEAT + (size_t)(k * TPB + tid) * FPITCH;
        *(uint4*)(base)      = A;
        *(uint4*)(base + 16) = B;
    }
    __syncwarp();   // warp consumes only its own rows

    // ---- per-lane biases (j-set shared by L0 and L1 epilogues) ----
    float myBa0[8], myBb0[8], myBa1[8], myBb1[8];
    #pragma unroll
    for (int p = 0; p < 8; p++) {
        const int j = (p >> 1) * 8 + 2 * q + (p & 1);
        myBa0[p] = ba0s[j];  myBb0[p] = bb0s[j];
        myBa1[p] = b1as[j];  myBb1[p] = b1bs[j];
    }

    const uint32_t f_base   = smem_u32(smem + SM_FEAT);
    const uint32_t w0_base  = smem_u32(smem + SM_W0B);
    const uint32_t w1h_base = smem_u32(smem + SM_W1H);
    const uint32_t w1l_base = smem_u32(smem + SM_W1L);

    #pragma unroll 1
    for (int T = 0; T < 4; T++) {
        // ---- L0 A fragments (16 features; reused for both B k-chunks) ----
        uint32_t Af0[2][4];
        #pragma unroll
        for (int mt = 0; mt < 2; mt++) {
            uint32_t addr = f_base
                + (uint32_t)(T * TPB + w * 32 + mt * 16 + (lane & 15)) * FPITCH
                + (lane >> 4) * 16;
            ldmatrix_x4(Af0[mt][0], Af0[mt][1], Af0[mt][2], Af0[mt][3], addr);
        }
        // ---- L0 B fragments (hi = kt0, lo = kt1) ----
        uint32_t Bf[8][2][2];
        #pragma unroll
        for (int kt = 0; kt < 2; kt++) {
            #pragma unroll
            for (int g = 0; g < 4; g++) {
                const int m  = lane >> 3;
                const int nt = 2 * g + (m >> 1);
                const int kq = m & 1;
                uint32_t off = (uint32_t)(nt * 8 + (lane & 7)) * WPITCH
                             + kt * 32 + kq * 16;
                ldmatrix_x4(Bf[2 * g][kt][0], Bf[2 * g][kt][1],
                            Bf[2 * g + 1][kt][0], Bf[2 * g + 1][kt][1],
                            w0_base + off);
            }
        }
        // ---- L0 MMA: D = A@W0hi + A@W0lo ----
        float d0[2][8][4];
        #pragma unroll
        for (int mt = 0; mt < 2; mt++)
            #pragma unroll
            for (int nt = 0; nt < 8; nt++) {
                #pragma unroll
                for (int c = 0; c < 4; c++) d0[mt][nt][c] = 0.0f;
                mma_bf16(d0[mt][nt], Af0[mt], Bf[nt][0][0], Bf[nt][0][1]);
                mma_bf16(d0[mt][nt], Af0[mt], Bf[nt][1][0], Bf[nt][1][1]);
            }
        // ---- u = tanh*tanh on fragments ----
        float u[2][4][4];
        #pragma unroll
        for (int mt = 0; mt < 2; mt++)
            #pragma unroll
            for (int nt = 0; nt < 4; nt++)
                #pragma unroll
                for (int c = 0; c < 4; c++) {
                    const int p = nt * 2 + (c & 1);
                    const float apre = d0[mt][nt][c]     + myBa0[p];
                    const float bpre = d0[mt][nt + 4][c] + myBb0[p];
                    u[mt][nt][c] = tanh_apx(apre) * tanh_apx(bpre);
                }
        // ---- repack u as L1 A fragments (in-register, no smem) ----
        uint32_t Af1[2][2][4];
        #pragma unroll
        for (int mt = 0; mt < 2; mt++)
            #pragma unroll
            for (int kt = 0; kt < 2; kt++) {
                Af1[mt][kt][0] = pk_bf2(u[mt][2 * kt][0],     u[mt][2 * kt][1]);
                Af1[mt][kt][1] = pk_bf2(u[mt][2 * kt][2],     u[mt][2 * kt][3]);
                Af1[mt][kt][2] = pk_bf2(u[mt][2 * kt + 1][0], u[mt][2 * kt + 1][1]);
                Af1[mt][kt][3] = pk_bf2(u[mt][2 * kt + 1][2], u[mt][2 * kt + 1][3]);
            }
        // ---- L1 MMA: D = u@W1hi + u@W1lo (two passes reuse Bf regs) ----
        float d1[2][8][4];
        #pragma unroll
        for (int mt = 0; mt < 2; mt++)
            #pragma unroll
            for (int nt = 0; nt < 8; nt++)
                #pragma unroll
                for (int c = 0; c < 4; c++) d1[mt][nt][c] = 0.0f;

        #pragma unroll
        for (int pass = 0; pass < 2; pass++) {
            const uint32_t wb = pass ? w1l_base : w1h_base;
            #pragma unroll
            for (int kt = 0; kt < 2; kt++) {
                #pragma unroll
                for (int g = 0; g < 4; g++) {
                    const int m  = lane >> 3;
                    const int nt = 2 * g + (m >> 1);
                    const int kq = m & 1;
                    uint32_t off = (uint32_t)(nt * 8 + (lane & 7)) * WPITCH
                                 + kt * 32 + kq * 16;
                    ldmatrix_x4(Bf[2 * g][kt][0], Bf[2 * g][kt][1],
                                Bf[2 * g + 1][kt][0], Bf[2 * g + 1][kt][1],
                                wb + off);
                }
            }
            #pragma unroll
            for (int mt = 0; mt < 2; mt++)
                #pragma unroll
                for (int nt = 0; nt < 8; nt++) {
                    mma_bf16(d1[mt][nt], Af1[mt][0], Bf[nt][0][0], Bf[nt][0][1]);
                    mma_bf16(d1[mt][nt], Af1[mt][1], Bf[nt][1][0], Bf[nt][1][1]);
                }
        }

        // ---- v = tanh*tanh ----
        float vv[4][8];
        #pragma unroll
        for (int s = 0; s < 4; s++) {
            const int mt = s >> 1, co = (s & 1) * 2;
            #pragma unroll
            for (int p = 0; p < 8; p++) {
                const int nt = p >> 1, e = p & 1;
                const float apre = d1[mt][nt][co + e]     + myBa1[p];
                const float bpre = d1[mt][nt + 4][co + e] + myBb1[p];
                vv[s][p] = tanh_apx(apre) * tanh_apx(bpre);
            }
        }

        // ---- heads partial sums ----
        ull H[4][4];
        #pragma unroll
        for (int s = 0; s < 4; s++)
            #pragma unroll
            for (int m = 0; m < 4; m++) H[s][m] = 0ULL;

        #pragma unroll
        for (int p = 0; p < 8; p++) {
            const int j = (p >> 1) * 8 + 2 * q + (p & 1);
            const ull hw0 = sH[j * 4 + 0], hw1 = sH[j * 4 + 1];
            const ull hw2 = sH[j * 4 + 2], hw3 = sH[j * 4 + 3];
            #pragma unroll
            for (int s = 0; s < 4; s++) {
                const ull vd = dup(vv[s][p]);
                ffma2(H[s][0], vd, hw0);
                ffma2(H[s][1], vd, hw1);
                ffma2(H[s][2], vd, hw2);
                ffma2(H[s][3], vd, hw3);
            }
        }

        // ---- butterfly reduce over the 4-lane column group ----
        #pragma unroll
        for (int mask = 1; mask <= 2; mask <<= 1) {
            #pragma unroll
            for (int s = 0; s < 4; s++)
                #pragma unroll
                for (int m = 0; m < 4; m++) {
                    ull o = __shfl_xor_sync(0xffffffffu, H[s][m], mask);
                    H[s][m] = add2(H[s][m], o);
                }
        }

        // ---- tail: lane handles token slot q ----
        {
            const int r = ((q >> 1) * 16) + ((q & 1) * 8) + (lane >> 2);
            const int t = tb + T * TPB + w * 32 + r;

            const ull Hf0 = add2(H[q][0], sAin[0]);
            const ull Hf1 = add2(H[q][1], sAin[1]);
            const ull Hf2 = add2(H[q][2], sAin[2]);
            const ull Hf3 = add2(H[q][3], sAin[3]);

            float sa, sb, sg, c0, c1, c2, c3, c4;
            upk(sa, sb, Hf0);
            upk(sg, c0, Hf1);
            upk(c1, c2, Hf2);
            upk(c3, c4, Hf3);

            const float* dxp = delta_x + (size_t)t * 6;
            const float* hp  = h_prev  + (size_t)t * SD;
            const float d0x = dxp[0], d1x = dxp[1], d2x = dxp[2];

            const float alpha = __expf(sa);
            const float beta  = __expf(sb);
            const float gamma = __expf(sg);
            const float zarg = fmaf(alpha, fabsf(d0x), fmaf(beta, d1x, gamma * fabsf(d2x)));
            const float z = 1.0f - __expf(-zarg);

            float c[SD] = { c0, c1, c2, c3, c4 };
            float sigma = 0.0f;
            #pragma unroll
            for (int dd = 0; dd < SD; dd++) {
                const float hv = hp[dd];
                const float cn = tanh_apx(c[dd]);
                const float hn = fmaf(z, cn - hv, hv);
                out[(size_t)t * SD + dd] = hn;
                sigma = fmaf(hn, sWout[dd], sigma);
            }
            out[(size_t)NTOK * SD + t] = sigma;
        }
    }
}

extern "C" void kernel_launch(void* const* d_in, const int* in_sizes, int n_in,
                              void* d_out, int out_size) {
    const float* h_prev  = (const float*)d_in[0];
    const float* delta_x = (const float*)d_in[1];
    const float* Wa0     = (const float*)d_in[2];
    const float* ba0     = (const float*)d_in[3];
    const float* Wb0     = (const float*)d_in[4];
    const float* bb0     = (const float*)d_in[5];
    const float* Wa1     = (const float*)d_in[6];
    const float* ba1     = (const float*)d_in[7];
    const float* Wb1     = (const float*)d_in[8];
    const float* bb1     = (const float*)d_in[9];
    const float* W_alpha = (const float*)d_in[10];
    const float* b_alpha = (const float*)d_in[11];
    const float* W_beta  = (const float*)d_in[12];
    const float* b_beta  = (const float*)d_in[13];
    const float* W_gamma = (const float*)d_in[14];
    const float* b_gamma = (const float*)d_in[15];
    const float* W_c     = (const float*)d_in[16];
    const float* b_c     = (const float*)d_in[17];
    const float* W_out   = (const float*)d_in[18];
    float* out = (float*)d_out;

    cumsum_kernel<<<BATCH, 1024>>>(delta_x);
    msc_main<<<NTOK / TOKS_PER_BLOCK, TPB, SM_TOTAL>>>(
        h_prev, delta_x,
        Wa0, ba0, Wb0, bb0,
        Wa1, ba1, Wb1, bb1,
        W_alpha, b_alpha, W_beta, b_beta,
        W_gamma, b_gamma, W_c, b_c, W_out,
        out);
}